// round 3
// baseline (speedup 1.0000x reference)
#include <cuda_runtime.h>
#include <math.h>

#define B_ 256
#define M_ 200000
#define D_ 384
#define H_ 512
#define KK_ 5
#define MT_ 128
#define NCHUNK_ 1563   /* ceil(200000/128) */

// ---------------- scratch (device globals; no runtime allocation) ----------
__device__ float g_center[2];
__device__ float g_act[M_];
__device__ float g_rnorm[M_];
__device__ float g_qnT[D_ * B_];                       // transposed normalized queries [d][b]
__device__ float g_pvals[(size_t)B_ * NCHUNK_ * KK_];  // per-chunk partial top5 values
__device__ int   g_pidx[(size_t)B_ * NCHUNK_ * KK_];   // per-chunk partial top5 indices
__device__ int   g_topk[B_ * KK_];                     // final top5 indices (desc)
__device__ float g_xp[(size_t)B_ * 6 * H_];            // x_proj [b][t][h]
__device__ float g_gate[B_ * H_];
__device__ float g_h[2][B_ * H_];                      // RNN ping-pong

// total order: (value desc, index asc) — matches jax.lax.top_k tie behavior
__device__ __forceinline__ void top5_insert(float v, int idx, float* bv, int* bi) {
    if (v < bv[4]) return;
    if (v == bv[4] && idx >= bi[4]) return;
#pragma unroll
    for (int j = 0; j < 5; j++) {
        bool better = (v > bv[j]) || (v == bv[j] && idx < bi[j]);
        if (better) {
#pragma unroll
            for (int q = 4; q > j; q--) { bv[q] = bv[q - 1]; bi[q] = bi[q - 1]; }
            bv[j] = v; bi[j] = idx;
            break;
        }
    }
}

// ---------------- phase 0: center of spatial_weights ----------------------
__global__ void k_center(const float* __restrict__ sw) {
    __shared__ float sx[8], sy[8];
    int tid = threadIdx.x;
    float ax = 0.f, ay = 0.f;
    for (int i = tid; i < H_; i += 256) { ax += sw[2 * i]; ay += sw[2 * i + 1]; }
    for (int o = 16; o > 0; o >>= 1) {
        ax += __shfl_down_sync(0xffffffffu, ax, o);
        ay += __shfl_down_sync(0xffffffffu, ay, o);
    }
    if ((tid & 31) == 0) { sx[tid >> 5] = ax; sy[tid >> 5] = ay; }
    __syncthreads();
    if (tid == 0) {
        float tx = 0.f, ty = 0.f;
        for (int w = 0; w < 8; w++) { tx += sx[w]; ty += sy[w]; }
        g_center[0] = tx / (float)H_;
        g_center[1] = ty / (float)H_;
    }
}

// ---------------- phase 1a: spatial activations ---------------------------
__global__ void k_act(const float* __restrict__ coords) {
    int i = blockIdx.x * 256 + threadIdx.x;
    if (i >= M_) return;
    float2 c = ((const float2*)coords)[i];
    float dx = c.x - g_center[0], dy = c.y - g_center[1];
    g_act[i] = 1.0f / (1.0f + sqrtf(dx * dx + dy * dy));
}

// ---------------- phase 1b: memory-vector inverse norms -------------------
__global__ void k_rnorm(const float* __restrict__ mv) {
    int warp = threadIdx.x >> 5, lane = threadIdx.x & 31;
    int row = blockIdx.x * 8 + warp;
    if (row >= M_) return;
    const float4* p = (const float4*)(mv + (size_t)row * D_);
    float s = 0.f;
#pragma unroll
    for (int i = 0; i < 3; i++) {  // 96 float4 per row
        float4 v = p[lane + 32 * i];
        s += v.x * v.x + v.y * v.y + v.z * v.z + v.w * v.w;
    }
    for (int o = 16; o > 0; o >>= 1) s += __shfl_down_sync(0xffffffffu, s, o);
    if (lane == 0) g_rnorm[row] = 1.0f / fmaxf(sqrtf(s), 1e-8f);
}

// ---------------- phase 1c: normalized, transposed queries ----------------
__global__ void k_qnT(const float* __restrict__ q) {
    int b = blockIdx.x, tid = threadIdx.x;  // 128 threads
    __shared__ float sred[4];
    __shared__ float sinv;
    float s = 0.f;
    for (int d = tid; d < D_; d += 128) { float v = q[(size_t)b * D_ + d]; s += v * v; }
    for (int o = 16; o > 0; o >>= 1) s += __shfl_down_sync(0xffffffffu, s, o);
    if ((tid & 31) == 0) sred[tid >> 5] = s;
    __syncthreads();
    if (tid == 0) {
        float t = sred[0] + sred[1] + sred[2] + sred[3];
        sinv = 1.0f / fmaxf(sqrtf(t), 1e-8f);
    }
    __syncthreads();
    float inv = sinv;
    for (int d = tid; d < D_; d += 128) g_qnT[d * B_ + b] = q[(size_t)b * D_ + d] * inv;
}

// ---------------- phase 2: sim GEMM + fused per-tile top-5 ----------------
// 128(b) x 128(m) tile per block, K-tiles of 32, 8x8 register blocking.
__global__ __launch_bounds__(256, 2) void k_sim(const float* __restrict__ mv) {
    extern __shared__ float sm[];
    float* As = sm;              // [32][128]  qnT slab (d-major)
    float* Bs = sm + 32 * 128;   // [32][128]  mv tile transposed (d-major)
    const int chunk = blockIdx.x, btile = blockIdx.y;
    const int m0 = chunk * MT_, b0 = btile * 128;
    const int tid = threadIdx.x;
    const int tx = tid & 15, ty = tid >> 4;

    float acc[8][8];
#pragma unroll
    for (int i = 0; i < 8; i++)
#pragma unroll
        for (int j = 0; j < 8; j++) acc[i][j] = 0.f;

    for (int k0 = 0; k0 < D_; k0 += 32) {
        __syncthreads();
        // load A slab: qnT already d-major -> conflict-free float4 stores
#pragma unroll
        for (int i = 0; i < 4; i++) {
            int p = tid + 256 * i;
            int kk = p >> 5, c4 = (p & 31) * 4;
            *(float4*)(As + kk * 128 + c4) =
                *(const float4*)(g_qnT + (k0 + kk) * B_ + b0 + c4);
        }
        // load B tile (memory vectors), transpose on store
#pragma unroll
        for (int i = 0; i < 4; i++) {
            int p = tid + 256 * i;
            int mr = p >> 3, d4 = (p & 7) * 4;
            int mg = m0 + mr; if (mg >= M_) mg = M_ - 1;
            float4 v = *(const float4*)(mv + (size_t)mg * D_ + k0 + d4);
            Bs[(d4 + 0) * 128 + mr] = v.x;
            Bs[(d4 + 1) * 128 + mr] = v.y;
            Bs[(d4 + 2) * 128 + mr] = v.z;
            Bs[(d4 + 3) * 128 + mr] = v.w;
        }
        __syncthreads();
#pragma unroll
        for (int kk = 0; kk < 32; kk++) {
            float a[8], b[8];
            *(float4*)(a)     = *(const float4*)(As + kk * 128 + ty * 8);
            *(float4*)(a + 4) = *(const float4*)(As + kk * 128 + ty * 8 + 4);
            *(float4*)(b)     = *(const float4*)(Bs + kk * 128 + tx * 8);
            *(float4*)(b + 4) = *(const float4*)(Bs + kk * 128 + tx * 8 + 4);
#pragma unroll
            for (int i = 0; i < 8; i++)
#pragma unroll
                for (int j = 0; j < 8; j++)
                    acc[i][j] = fmaf(a[i], b[j], acc[i][j]);
        }
    }
    __syncthreads();

    // epilogue: sim = acc * rnorm[m] + act[m]; stage tile in smem (reused)
    float* ssim = sm;  // [128][129]
#pragma unroll
    for (int j = 0; j < 8; j++) {
        int ml = tx * 8 + j, mg = m0 + ml;
        bool valid = (mg < M_);
        float rn = valid ? g_rnorm[mg] : 0.f;
        float ac = valid ? g_act[mg] : 0.f;
#pragma unroll
        for (int i = 0; i < 8; i++) {
            float s = valid ? fmaf(acc[i][j], rn, ac) : -INFINITY;
            ssim[(ty * 8 + i) * 129 + ml] = s;
        }
    }
    __syncthreads();

    // per-row top-5 over the 128 columns of this tile
    if (tid < 128) {
        float bv[5] = {-INFINITY, -INFINITY, -INFINITY, -INFINITY, -INFINITY};
        int   bi[5] = {0x7fffffff, 0x7fffffff, 0x7fffffff, 0x7fffffff, 0x7fffffff};
        for (int c = 0; c < 128; c++)
            top5_insert(ssim[tid * 129 + c], m0 + c, bv, bi);
        size_t base = ((size_t)(b0 + tid) * NCHUNK_ + chunk) * KK_;
#pragma unroll
        for (int j = 0; j < 5; j++) { g_pvals[base + j] = bv[j]; g_pidx[base + j] = bi[j]; }
    }
}

// ---------------- phase 3: merge partial top-5 across chunks --------------
__global__ void k_merge() {
    int b = blockIdx.x, lane = threadIdx.x;  // 32 threads
    float bv[5] = {-INFINITY, -INFINITY, -INFINITY, -INFINITY, -INFINITY};
    int   bi[5] = {0x7fffffff, 0x7fffffff, 0x7fffffff, 0x7fffffff, 0x7fffffff};
    const float* pv = g_pvals + (size_t)b * NCHUNK_ * KK_;
    const int*   pi = g_pidx + (size_t)b * NCHUNK_ * KK_;
    for (int j = lane; j < NCHUNK_ * KK_; j += 32)
        top5_insert(pv[j], pi[j], bv, bi);
    __shared__ float sv[160];
    __shared__ int   si[160];
#pragma unroll
    for (int j = 0; j < 5; j++) { sv[lane * 5 + j] = bv[j]; si[lane * 5 + j] = bi[j]; }
    __syncthreads();
    if (lane == 0) {
        float fv[5] = {-INFINITY, -INFINITY, -INFINITY, -INFINITY, -INFINITY};
        int   fi[5] = {0x7fffffff, 0x7fffffff, 0x7fffffff, 0x7fffffff, 0x7fffffff};
        for (int j = 0; j < 160; j++) top5_insert(sv[j], si[j], fv, fi);
#pragma unroll
        for (int j = 0; j < 5; j++) g_topk[b * 5 + j] = fi[j];
    }
}

// ---------------- phase 4: projections (x_proj with gather / gate) --------
// mode 0: rows = (b,t) pairs (1536), W=W_ih,  out=g_xp
// mode 1: rows = b (256),           W=gate_W, out=g_gate (sigmoid)
__global__ void k_proj(const float* __restrict__ query, const float* __restrict__ mv,
                       const float* __restrict__ W, const float* __restrict__ bias,
                       int mode) {
    __shared__ float sin_[16][D_];
    __shared__ const float* srcp[16];
    int r0 = blockIdx.x * 16, h0 = blockIdx.y * 128;
    int tid = threadIdx.x;  // 256
    if (tid < 16) {
        int r = r0 + tid;
        const float* s;
        if (mode == 0) {
            int b = r / 6, t = r - b * 6;
            s = (t == 0) ? (query + (size_t)b * D_)
                         : (mv + (size_t)g_topk[b * 5 + (t - 1)] * D_);
        } else {
            s = query + (size_t)r * D_;
        }
        srcp[tid] = s;
    }
    __syncthreads();
    for (int e = tid; e < 16 * D_; e += 256) {
        int rr = e / D_, d = e - rr * D_;
        sin_[rr][d] = srcp[rr][d];
    }
    __syncthreads();
    int h = h0 + (tid & 127);
    int rg = tid >> 7;  // 0/1 -> rows rg*8 .. rg*8+7
    float acc[8];
    float bb = bias[h];
#pragma unroll
    for (int r = 0; r < 8; r++) acc[r] = bb;
    for (int d = 0; d < D_; d += 4) {
        float4 w = *(const float4*)(W + (size_t)h * D_ + d);
#pragma unroll
        for (int r = 0; r < 8; r++) {
            float4 x = *(const float4*)(&sin_[rg * 8 + r][d]);
            acc[r] = fmaf(w.x, x.x, fmaf(w.y, x.y, fmaf(w.z, x.z, fmaf(w.w, x.w, acc[r]))));
        }
    }
    float* out = (mode == 0) ? g_xp : g_gate;
#pragma unroll
    for (int r = 0; r < 8; r++) {
        float v = acc[r];
        if (mode == 1) v = 1.0f / (1.0f + expf(-v));
        out[(size_t)(r0 + rg * 8 + r) * H_ + h] = v;
    }
}

// ---------------- phase 5: RNN step ---------------------------------------
__global__ void k_rnn(const float* __restrict__ W_hh, const float* __restrict__ b_hh,
                      int t) {
    __shared__ float sh[16][H_];
    int b0 = blockIdx.x * 16, h0 = blockIdx.y * 128;
    int tid = threadIdx.x;  // 256
    const float* hprev = g_h[(t + 1) & 1];
    float* hnext = g_h[t & 1];
    if (t > 0) {
        for (int e = tid; e < 16 * H_; e += 256) {
            int rr = e >> 9, k = e & 511;
            sh[rr][k] = hprev[(size_t)(b0 + rr) * H_ + k];
        }
    }
    __syncthreads();
    int h = h0 + (tid & 127);
    int rg = tid >> 7;
    float acc[8];
    float bb = b_hh[h];
#pragma unroll
    for (int r = 0; r < 8; r++)
        acc[r] = g_xp[((size_t)(b0 + rg * 8 + r) * 6 + t) * H_ + h] + bb;
    if (t > 0) {
        for (int k = 0; k < H_; k += 4) {
            float4 w = *(const float4*)(W_hh + (size_t)h * H_ + k);
#pragma unroll
            for (int r = 0; r < 8; r++) {
                float4 x = *(const float4*)(&sh[rg * 8 + r][k]);
                acc[r] = fmaf(w.x, x.x, fmaf(w.y, x.y, fmaf(w.z, x.z, fmaf(w.w, x.w, acc[r]))));
            }
        }
    }
#pragma unroll
    for (int r = 0; r < 8; r++)
        hnext[(size_t)(b0 + rg * 8 + r) * H_ + h] = tanhf(acc[r]);
}

// ---------------- phase 6: gated output -----------------------------------
__global__ void k_final(float* __restrict__ out) {
    int i = blockIdx.x * 256 + threadIdx.x;
    if (i >= B_ * H_) return;
    int b = i >> 9, h = i & 511;
    float g = g_gate[i];
    out[i] = g * g_h[1][i] + (1.0f - g) * g_xp[(size_t)b * 6 * H_ + h];
}

// ---------------- launcher -------------------------------------------------
extern "C" void kernel_launch(void* const* d_in, const int* in_sizes, int n_in,
                              void* d_out, int out_size) {
    const float* query  = (const float*)d_in[0];
    const float* mv     = (const float*)d_in[1];
    const float* coords = (const float*)d_in[2];
    const float* sw     = (const float*)d_in[3];
    const float* W_ih   = (const float*)d_in[4];
    const float* b_ih   = (const float*)d_in[5];
    const float* W_hh   = (const float*)d_in[6];
    const float* b_hh   = (const float*)d_in[7];
    const float* gW     = (const float*)d_in[8];
    const float* gb     = (const float*)d_in[9];
    float* out = (float*)d_out;
    (void)in_sizes; (void)n_in; (void)out_size;

    cudaFuncSetAttribute(k_sim, cudaFuncAttributeMaxDynamicSharedMemorySize, 128 * 129 * 4);

    k_center<<<1, 256>>>(sw);
    k_act<<<(M_ + 255) / 256, 256>>>(coords);
    k_rnorm<<<M_ / 8, 256>>>(mv);
    k_qnT<<<B_, 128>>>(query);
    k_sim<<<dim3(NCHUNK_, 2), 256, 128 * 129 * 4>>>(mv);
    k_merge<<<B_, 32>>>();
    k_proj<<<dim3(96, 4), 256>>>(query, mv, W_ih, b_ih, 0);
    k_proj<<<dim3(16, 4), 256>>>(query, mv, gW, gb, 1);
    for (int t = 0; t < 6; t++)
        k_rnn<<<dim3(16, 4), 256>>>(W_hh, b_hh, t);
    k_final<<<(B_ * H_ + 255) / 256, 256>>>(out);
}

// round 8
// speedup vs baseline: 1.7312x; 1.7312x over previous
#include <cuda_runtime.h>
#include <cuda_bf16.h>
#include <math.h>
#include <cstdint>

#define B_ 256
#define M_ 200000
#define D_ 384
#define H_ 512
#define NCH_ 1563        /* ceil(200000/128) */
#define CAND_ 16
#define STG_ 49152       /* per-stage smem bytes: A 32KB + B 16KB */

// ---------------- device scratch ------------------------------------------
__device__ float g_center[2];
__device__ float g_act[M_];
__device__ __align__(16) float g_qn[B_ * D_];            // normalized queries fp32
__device__ __align__(16) __nv_bfloat16 g_qnb[B_ * D_];   // normalized queries bf16
__device__ __align__(16) __nv_bfloat16 g_mvb[(size_t)M_ * D_];  // normalized mv bf16
__device__ float g_pvals[(size_t)B_ * NCH_ * 4];
__device__ int   g_pidx[(size_t)B_ * NCH_ * 4];
__device__ int   g_cand[B_ * CAND_];
__device__ int   g_topk[B_ * 5];
__device__ float g_xp[(size_t)B_ * 6 * H_];
__device__ float g_gate[B_ * H_];
__device__ float g_h[2][B_ * H_];

// total order (value desc, index asc) — jax.lax.top_k tie behavior
template <int NN>
__device__ __forceinline__ void topn_insert(float v, int idx, float* bv, int* bi) {
    if (v < bv[NN - 1] || (v == bv[NN - 1] && idx >= bi[NN - 1])) return;
#pragma unroll
    for (int j = 0; j < NN; j++) {
        if (v > bv[j] || (v == bv[j] && idx < bi[j])) {
#pragma unroll
            for (int q = NN - 1; q > j; q--) { bv[q] = bv[q - 1]; bi[q] = bi[q - 1]; }
            bv[j] = v; bi[j] = idx;
            break;
        }
    }
}

// ---------------- PTX helpers (sm_80-era only; no tcgen05) -----------------
__device__ __forceinline__ uint32_t s2u(const void* p) {
    return (uint32_t)__cvta_generic_to_shared(p);
}
__device__ __forceinline__ void cp16(uint32_t saddr, const void* g) {
    asm volatile("cp.async.cg.shared.global [%0], [%1], 16;\n" :: "r"(saddr), "l"(g));
}
#define CP_COMMIT() asm volatile("cp.async.commit_group;\n" ::: "memory")
#define CP_WAIT(n)  asm volatile("cp.async.wait_group %0;\n" :: "n"(n) : "memory")

__device__ __forceinline__ void ldsm4(uint32_t& r0, uint32_t& r1, uint32_t& r2,
                                      uint32_t& r3, uint32_t a) {
    asm volatile("ldmatrix.sync.aligned.m8n8.x4.shared.b16 {%0,%1,%2,%3}, [%4];"
                 : "=r"(r0), "=r"(r1), "=r"(r2), "=r"(r3) : "r"(a));
}
__device__ __forceinline__ void mma_bf16(float* c, uint32_t a0, uint32_t a1,
                                         uint32_t a2, uint32_t a3,
                                         uint32_t b0, uint32_t b1) {
    asm volatile(
        "mma.sync.aligned.m16n8k16.row.col.f32.bf16.bf16.f32 "
        "{%0,%1,%2,%3}, {%4,%5,%6,%7}, {%8,%9}, {%0,%1,%2,%3};"
        : "+f"(c[0]), "+f"(c[1]), "+f"(c[2]), "+f"(c[3])
        : "r"(a0), "r"(a1), "r"(a2), "r"(a3), "r"(b0), "r"(b1));
}

// ---------------- phase 0/1: center, activations ---------------------------
__global__ void k_center(const float* __restrict__ sw) {
    __shared__ float sx[8], sy[8];
    int tid = threadIdx.x;
    float ax = 0.f, ay = 0.f;
    for (int i = tid; i < H_; i += 256) { ax += sw[2 * i]; ay += sw[2 * i + 1]; }
    for (int o = 16; o > 0; o >>= 1) {
        ax += __shfl_down_sync(0xffffffffu, ax, o);
        ay += __shfl_down_sync(0xffffffffu, ay, o);
    }
    if ((tid & 31) == 0) { sx[tid >> 5] = ax; sy[tid >> 5] = ay; }
    __syncthreads();
    if (tid == 0) {
        float tx = 0.f, ty = 0.f;
        for (int w = 0; w < 8; w++) { tx += sx[w]; ty += sy[w]; }
        g_center[0] = tx / (float)H_;
        g_center[1] = ty / (float)H_;
    }
}

__global__ void k_act(const float* __restrict__ coords) {
    int i = blockIdx.x * 256 + threadIdx.x;
    if (i >= M_) return;
    float2 c = ((const float2*)coords)[i];
    float dx = c.x - g_center[0], dy = c.y - g_center[1];
    g_act[i] = 1.0f / (1.0f + sqrtf(dx * dx + dy * dy));
}

// ---------------- phase 1b: mv -> normalized bf16 copy ---------------------
__global__ void k_conv(const float* __restrict__ mv) {
    int row = blockIdx.x * 8 + (threadIdx.x >> 5);
    int lane = threadIdx.x & 31;
    const float4* p = (const float4*)(mv + (size_t)row * D_);
    float4 v[3];
    float ss = 0.f;
#pragma unroll
    for (int r = 0; r < 3; r++) {
        v[r] = p[lane + 32 * r];
        ss += v[r].x * v[r].x + v[r].y * v[r].y + v[r].z * v[r].z + v[r].w * v[r].w;
    }
#pragma unroll
    for (int o = 16; o > 0; o >>= 1) ss += __shfl_xor_sync(0xffffffffu, ss, o);
    float rn = 1.0f / fmaxf(sqrtf(ss), 1e-8f);
    __nv_bfloat16* ob = g_mvb + (size_t)row * D_;
#pragma unroll
    for (int r = 0; r < 3; r++) {
        int e = r * 128 + lane * 4;
        *reinterpret_cast<__nv_bfloat162*>(ob + e) =
            __nv_bfloat162(__float2bfloat16_rn(v[r].x * rn), __float2bfloat16_rn(v[r].y * rn));
        *reinterpret_cast<__nv_bfloat162*>(ob + e + 2) =
            __nv_bfloat162(__float2bfloat16_rn(v[r].z * rn), __float2bfloat16_rn(v[r].w * rn));
    }
}

// ---------------- phase 1c: normalized queries (fp32 + bf16) ---------------
__global__ void k_qn(const float* __restrict__ q) {
    int b = blockIdx.x, tid = threadIdx.x;  // 128 threads
    __shared__ float sred[4];
    __shared__ float sinv;
    float s = 0.f;
    for (int d = tid; d < D_; d += 128) { float v = q[(size_t)b * D_ + d]; s += v * v; }
    for (int o = 16; o > 0; o >>= 1) s += __shfl_down_sync(0xffffffffu, s, o);
    if ((tid & 31) == 0) sred[tid >> 5] = s;
    __syncthreads();
    if (tid == 0) sinv = 1.0f / fmaxf(sqrtf(sred[0] + sred[1] + sred[2] + sred[3]), 1e-8f);
    __syncthreads();
    float inv = sinv;
    for (int d = tid; d < D_; d += 128) {
        float v = q[(size_t)b * D_ + d] * inv;
        g_qn[(size_t)b * D_ + d] = v;
        g_qnb[(size_t)b * D_ + d] = __float2bfloat16_rn(v);
    }
}

// ---------------- phase 2: bf16 mma.sync GEMM + fused approx top-4 ---------
// grid = NCH_ CTAs. CTA: all 256 queries (M) x 128 mvs (N), K=384.
// 8 warps: wr=wid&3 (M block of 64), wc=wid>>2 (N block of 64).
// smem stage: A 256x128B (32KB) + B 128x128B (16KB); 3 stages.
__global__ __launch_bounds__(256, 1) void k_simmma() {
    extern __shared__ char smc[];
    const uint32_t sbase = s2u(smc);
    const int tid = threadIdx.x;
    const int wid = tid >> 5, lane = tid & 31;
    const int chunk = blockIdx.x;
    const int n0 = chunk * 128;
    const int mbase = (wid & 3) * 64, nbase = (wid >> 2) * 64;

    auto load_stage = [&](int kc, int st) {
        uint32_t sb = sbase + st * STG_;
#pragma unroll
        for (int i = 0; i < 8; i++) {  // A: 256 rows x 128B
            int e = tid + i * 256;
            int row = e >> 3, c = e & 7;
            cp16(sb + row * 128 + ((c * 16) ^ ((row & 7) << 4)),
                 g_qnb + (size_t)row * D_ + kc * 64 + c * 8);
        }
#pragma unroll
        for (int i = 0; i < 4; i++) {  // B: 128 rows x 128B
            int e = tid + i * 256;
            int row = e >> 3, c = e & 7;
            int mg = n0 + row; if (mg >= M_) mg = M_ - 1;
            cp16(sb + 32768 + row * 128 + ((c * 16) ^ ((row & 7) << 4)),
                 g_mvb + (size_t)mg * D_ + kc * 64 + c * 8);
        }
        CP_COMMIT();
    };

    load_stage(0, 0);
    load_stage(1, 1);

    float acc[4][8][4];
#pragma unroll
    for (int mt = 0; mt < 4; mt++)
#pragma unroll
        for (int nt = 0; nt < 8; nt++)
#pragma unroll
            for (int r = 0; r < 4; r++) acc[mt][nt][r] = 0.f;

    // per-lane ldmatrix row/col components
    const int g = lane >> 3;
    const int rA = (g & 1) * 8 + (lane & 7);   // A row offset, kex = (g>>1)*16
    const int kexA = (g >> 1) * 16;
    const int rB = (g >> 1) * 8 + (lane & 7);  // B row offset, kex = (g&1)*16
    const int kexB = (g & 1) * 16;

    for (int kc = 0; kc < 6; kc++) {
        if (kc < 5) { CP_WAIT(1); } else { CP_WAIT(0); }
        __syncthreads();
        if (kc <= 3) load_stage(kc + 2, (kc + 2) % 3);

        uint32_t sa = sbase + (kc % 3) * STG_;
        uint32_t sbb = sa + 32768;
#pragma unroll
        for (int ks = 0; ks < 4; ks++) {
            const int kb = ks * 32;
            uint32_t a[4][4], b[8][2];
#pragma unroll
            for (int mt = 0; mt < 4; mt++) {
                int row = mbase + mt * 16 + rA;
                uint32_t ad = sa + row * 128 + ((kb + kexA) ^ ((row & 7) << 4));
                ldsm4(a[mt][0], a[mt][1], a[mt][2], a[mt][3], ad);
            }
#pragma unroll
            for (int p = 0; p < 4; p++) {
                int row = nbase + p * 16 + rB;
                uint32_t bd = sbb + row * 128 + ((kb + kexB) ^ ((row & 7) << 4));
                ldsm4(b[2 * p][0], b[2 * p][1], b[2 * p + 1][0], b[2 * p + 1][1], bd);
            }
#pragma unroll
            for (int mt = 0; mt < 4; mt++)
#pragma unroll
                for (int nt = 0; nt < 8; nt++)
                    mma_bf16(acc[mt][nt], a[mt][0], a[mt][1], a[mt][2], a[mt][3],
                             b[nt][0], b[nt][1]);
        }
    }
    __syncthreads();

    // epilogue: stage C tile in smem [256][129] fp32, conflict-free scan
    float* sf = (float*)smc;
#pragma unroll
    for (int mt = 0; mt < 4; mt++) {
        int r = mbase + mt * 16 + (lane >> 2);
#pragma unroll
        for (int nt = 0; nt < 8; nt++) {
            int c = nbase + nt * 8 + (lane & 3) * 2;
            sf[r * 129 + c]           = acc[mt][nt][0];
            sf[r * 129 + c + 1]       = acc[mt][nt][1];
            sf[(r + 8) * 129 + c]     = acc[mt][nt][2];
            sf[(r + 8) * 129 + c + 1] = acc[mt][nt][3];
        }
    }
    __syncthreads();

    // per-query (thread = query row) top-4 over this chunk's 128 cols
    {
        float bv[4] = {-INFINITY, -INFINITY, -INFINITY, -INFINITY};
        int   bi[4] = {0x7fffffff, 0x7fffffff, 0x7fffffff, 0x7fffffff};
        for (int c = 0; c < 128; c++) {
            int mg = n0 + c;
            if (mg < M_) {
                float s = sf[tid * 129 + c] + __ldg(&g_act[mg]);
                topn_insert<4>(s, mg, bv, bi);
            }
        }
        size_t base = ((size_t)tid * NCH_ + chunk) * 4;
#pragma unroll
        for (int j = 0; j < 4; j++) { g_pvals[base + j] = bv[j]; g_pidx[base + j] = bi[j]; }
    }
}

// ---------------- phase 3: merge approx partials -> top-16 candidates ------
__global__ void k_merge16() {
    int b = blockIdx.x, tid = threadIdx.x;  // 64 threads
    float bv[CAND_]; int bi[CAND_];
#pragma unroll
    for (int j = 0; j < CAND_; j++) { bv[j] = -INFINITY; bi[j] = 0x7fffffff; }
    const float* pv = g_pvals + (size_t)b * NCH_ * 4;
    const int*   pi = g_pidx + (size_t)b * NCH_ * 4;
    for (int j = tid; j < NCH_ * 4; j += 64) topn_insert<CAND_>(pv[j], pi[j], bv, bi);
    __shared__ float sv[64 * CAND_];
    __shared__ int   si[64 * CAND_];
#pragma unroll
    for (int j = 0; j < CAND_; j++) { sv[tid * CAND_ + j] = bv[j]; si[tid * CAND_ + j] = bi[j]; }
    __syncthreads();
    if (tid == 0) {
        float fv[CAND_]; int fi[CAND_];
#pragma unroll
        for (int j = 0; j < CAND_; j++) { fv[j] = -INFINITY; fi[j] = 0x7fffffff; }
        for (int j = 0; j < 64 * CAND_; j++) topn_insert<CAND_>(sv[j], si[j], fv, fi);
#pragma unroll
        for (int j = 0; j < CAND_; j++) g_cand[b * CAND_ + j] = fi[j];
    }
}

// ---------------- phase 4: exact fp32 rescore -> top-5 ---------------------
__global__ void k_rescore(const float* __restrict__ mv) {
    int b = blockIdx.x, tid = threadIdx.x;  // 128 threads, 4 warps
    int w = tid >> 5, lane = tid & 31;
    __shared__ float qrow[D_];
    __shared__ float sval[CAND_];
    __shared__ int   sidx[CAND_];
    for (int d = tid; d < D_; d += 128) qrow[d] = g_qn[(size_t)b * D_ + d];
    __syncthreads();
    for (int c = w; c < CAND_; c += 4) {
        int idx = g_cand[b * CAND_ + c];
        const float4* mp = (const float4*)(mv + (size_t)idx * D_);
        const float4* qp = (const float4*)qrow;
        float dot = 0.f, ss = 0.f;
#pragma unroll
        for (int r = 0; r < 3; r++) {
            float4 m = mp[lane + 32 * r], q = qp[lane + 32 * r];
            dot += q.x * m.x + q.y * m.y + q.z * m.z + q.w * m.w;
            ss  += m.x * m.x + m.y * m.y + m.z * m.z + m.w * m.w;
        }
        for (int o = 16; o > 0; o >>= 1) {
            dot += __shfl_down_sync(0xffffffffu, dot, o);
            ss  += __shfl_down_sync(0xffffffffu, ss, o);
        }
        if (lane == 0) {
            sval[c] = dot / fmaxf(sqrtf(ss), 1e-8f) + g_act[idx];
            sidx[c] = idx;
        }
    }
    __syncthreads();
    if (tid == 0) {
        float fv[5] = {-INFINITY, -INFINITY, -INFINITY, -INFINITY, -INFINITY};
        int   fi[5] = {0x7fffffff, 0x7fffffff, 0x7fffffff, 0x7fffffff, 0x7fffffff};
        for (int j = 0; j < CAND_; j++) topn_insert<5>(sval[j], sidx[j], fv, fi);
#pragma unroll
        for (int j = 0; j < 5; j++) g_topk[b * 5 + j] = fi[j];
    }
}

// ---------------- phase 5: projections --------------------------------------
__global__ void k_proj(const float* __restrict__ query, const float* __restrict__ mv,
                       const float* __restrict__ W, const float* __restrict__ bias,
                       int mode) {
    __shared__ float sin_[16][D_];
    __shared__ const float* srcp[16];
    int r0 = blockIdx.x * 16, h0 = blockIdx.y * 128;
    int tid = threadIdx.x;  // 256
    if (tid < 16) {
        int r = r0 + tid;
        const float* s;
        if (mode == 0) {
            int b = r / 6, t = r - b * 6;
            s = (t == 0) ? (query + (size_t)b * D_)
                         : (mv + (size_t)g_topk[b * 5 + (t - 1)] * D_);
        } else {
            s = query + (size_t)r * D_;
        }
        srcp[tid] = s;
    }
    __syncthreads();
    for (int e = tid; e < 16 * D_; e += 256) {
        int rr = e / D_, d = e - rr * D_;
        sin_[rr][d] = srcp[rr][d];
    }
    __syncthreads();
    int h = h0 + (tid & 127);
    int rg = tid >> 7;
    float acc[8];
    float bb = bias[h];
#pragma unroll
    for (int r = 0; r < 8; r++) acc[r] = bb;
    for (int d = 0; d < D_; d += 4) {
        float4 w = *(const float4*)(W + (size_t)h * D_ + d);
#pragma unroll
        for (int r = 0; r < 8; r++) {
            float4 x = *(const float4*)(&sin_[rg * 8 + r][d]);
            acc[r] = fmaf(w.x, x.x, fmaf(w.y, x.y, fmaf(w.z, x.z, fmaf(w.w, x.w, acc[r]))));
        }
    }
    float* out = (mode == 0) ? g_xp : g_gate;
#pragma unroll
    for (int r = 0; r < 8; r++) {
        float v = acc[r];
        if (mode == 1) v = 1.0f / (1.0f + expf(-v));
        out[(size_t)(r0 + rg * 8 + r) * H_ + h] = v;
    }
}

// ---------------- phase 6: RNN step -----------------------------------------
__global__ void k_rnn(const float* __restrict__ W_hh, const float* __restrict__ b_hh,
                      int t) {
    __shared__ float sh[16][H_];
    int b0 = blockIdx.x * 16, h0 = blockIdx.y * 128;
    int tid = threadIdx.x;  // 256
    const float* hprev = g_h[(t + 1) & 1];
    float* hnext = g_h[t & 1];
    if (t > 0) {
        for (int e = tid; e < 16 * H_; e += 256) {
            int rr = e >> 9, k = e & 511;
            sh[rr][k] = hprev[(size_t)(b0 + rr) * H_ + k];
        }
    }
    __syncthreads();
    int h = h0 + (tid & 127);
    int rg = tid >> 7;
    float acc[8];
    float bb = b_hh[h];
#pragma unroll
    for (int r = 0; r < 8; r++)
        acc[r] = g_xp[((size_t)(b0 + rg * 8 + r) * 6 + t) * H_ + h] + bb;
    if (t > 0) {
        for (int k = 0; k < H_; k += 4) {
            float4 w = *(const float4*)(W_hh + (size_t)h * H_ + k);
#pragma unroll
            for (int r = 0; r < 8; r++) {
                float4 x = *(const float4*)(&sh[rg * 8 + r][k]);
                acc[r] = fmaf(w.x, x.x, fmaf(w.y, x.y, fmaf(w.z, x.z, fmaf(w.w, x.w, acc[r]))));
            }
        }
    }
#pragma unroll
    for (int r = 0; r < 8; r++)
        hnext[(size_t)(b0 + rg * 8 + r) * H_ + h] = tanhf(acc[r]);
}

// ---------------- phase 7: gated output --------------------------------------
__global__ void k_final(float* __restrict__ out) {
    int i = blockIdx.x * 256 + threadIdx.x;
    if (i >= B_ * H_) return;
    int b = i >> 9, h = i & 511;
    float g = g_gate[i];
    out[i] = g * g_h[1][i] + (1.0f - g) * g_xp[(size_t)b * 6 * H_ + h];
}

// ---------------- launcher ----------------------------------------------------
extern "C" void kernel_launch(void* const* d_in, const int* in_sizes, int n_in,
                              void* d_out, int out_size) {
    const float* query  = (const float*)d_in[0];
    const float* mv     = (const float*)d_in[1];
    const float* coords = (const float*)d_in[2];
    const float* sw     = (const float*)d_in[3];
    const float* W_ih   = (const float*)d_in[4];
    const float* b_ih   = (const float*)d_in[5];
    const float* W_hh   = (const float*)d_in[6];
    const float* b_hh   = (const float*)d_in[7];
    const float* gW     = (const float*)d_in[8];
    const float* gb     = (const float*)d_in[9];
    float* out = (float*)d_out;
    (void)in_sizes; (void)n_in; (void)out_size;

    cudaFuncSetAttribute(k_simmma, cudaFuncAttributeMaxDynamicSharedMemorySize, 3 * STG_);

    k_center<<<1, 256>>>(sw);
    k_act<<<(M_ + 255) / 256, 256>>>(coords);
    k_conv<<<M_ / 8, 256>>>(mv);
    k_qn<<<B_, 128>>>(query);
    k_simmma<<<NCH_, 256, 3 * STG_>>>();
    k_merge16<<<B_, 64>>>();
    k_rescore<<<B_, 128>>>(mv);
    k_proj<<<dim3(96, 4), 256>>>(query, mv, W_ih, b_ih, 0);
    k_proj<<<dim3(16, 4), 256>>>(query, mv, gW, gb, 1);
    for (int t = 0; t < 6; t++)
        k_rnn<<<dim3(16, 4), 256>>>(W_hh, b_hh, t);
    k_final<<<(B_ * H_ + 255) / 256, 256>>>(out);
}